// round 2
// baseline (speedup 1.0000x reference)
#include <cuda_runtime.h>
#include <math.h>
#include <stdint.h>

// Problem constants (fixed-shape problem)
#define BB 8
#define TT 256
#define UU 65
#define VV 1024
#define UM1 64

#define NEG_HUGE -1e30f

// Scratch (no cudaMalloc allowed)
__device__ float g_lpb[BB * TT * UU];    // log p(blank)  [b,t,u]
__device__ float g_lpl[BB * TT * UM1];   // log p(label)  [b,t,u]
__device__ float g_cost[BB];

// ---------------------------------------------------------------------------
// Kernel 1: per-(b,t,u) row logsumexp over V=1024 + gather blank/label logits.
// One warp per row, 8 float4 loads per lane (32 floats in registers).
// Memory-bound: one streaming pass over 545 MB.
// ---------------------------------------------------------------------------
__global__ __launch_bounds__(256) void rnnt_lse_kernel(
    const float* __restrict__ acts,
    const int* __restrict__ labels)
{
    const int warp = (blockIdx.x * blockDim.x + threadIdx.x) >> 5;
    const int lane = threadIdx.x & 31;
    if (warp >= BB * TT * UU) return;

    const int row = warp;                 // row = b*T*U + t*U + u
    const int u   = row % UU;
    const int bt  = row / UU;             // b*T + t
    const int b   = bt / TT;

    const float4* __restrict__ p =
        reinterpret_cast<const float4*>(acts) + (size_t)row * (VV / 4);

    float4 v0 = p[lane];
    float4 v1 = p[lane + 32];
    float4 v2 = p[lane + 64];
    float4 v3 = p[lane + 96];
    float4 v4 = p[lane + 128];
    float4 v5 = p[lane + 160];
    float4 v6 = p[lane + 192];
    float4 v7 = p[lane + 224];

    // lane max
    float m = v0.x;
    m = fmaxf(m, v0.y); m = fmaxf(m, v0.z); m = fmaxf(m, v0.w);
    m = fmaxf(m, v1.x); m = fmaxf(m, v1.y); m = fmaxf(m, v1.z); m = fmaxf(m, v1.w);
    m = fmaxf(m, v2.x); m = fmaxf(m, v2.y); m = fmaxf(m, v2.z); m = fmaxf(m, v2.w);
    m = fmaxf(m, v3.x); m = fmaxf(m, v3.y); m = fmaxf(m, v3.z); m = fmaxf(m, v3.w);
    m = fmaxf(m, v4.x); m = fmaxf(m, v4.y); m = fmaxf(m, v4.z); m = fmaxf(m, v4.w);
    m = fmaxf(m, v5.x); m = fmaxf(m, v5.y); m = fmaxf(m, v5.z); m = fmaxf(m, v5.w);
    m = fmaxf(m, v6.x); m = fmaxf(m, v6.y); m = fmaxf(m, v6.z); m = fmaxf(m, v6.w);
    m = fmaxf(m, v7.x); m = fmaxf(m, v7.y); m = fmaxf(m, v7.z); m = fmaxf(m, v7.w);

    #pragma unroll
    for (int o = 16; o > 0; o >>= 1)
        m = fmaxf(m, __shfl_xor_sync(0xffffffffu, m, o));

    // sum of exp(x - m)
    float s = 0.f;
    s += __expf(v0.x - m); s += __expf(v0.y - m); s += __expf(v0.z - m); s += __expf(v0.w - m);
    s += __expf(v1.x - m); s += __expf(v1.y - m); s += __expf(v1.z - m); s += __expf(v1.w - m);
    s += __expf(v2.x - m); s += __expf(v2.y - m); s += __expf(v2.z - m); s += __expf(v2.w - m);
    s += __expf(v3.x - m); s += __expf(v3.y - m); s += __expf(v3.z - m); s += __expf(v3.w - m);
    s += __expf(v4.x - m); s += __expf(v4.y - m); s += __expf(v4.z - m); s += __expf(v4.w - m);
    s += __expf(v5.x - m); s += __expf(v5.y - m); s += __expf(v5.z - m); s += __expf(v5.w - m);
    s += __expf(v6.x - m); s += __expf(v6.y - m); s += __expf(v6.z - m); s += __expf(v6.w - m);
    s += __expf(v7.x - m); s += __expf(v7.y - m); s += __expf(v7.z - m); s += __expf(v7.w - m);

    #pragma unroll
    for (int o = 16; o > 0; o >>= 1)
        s += __shfl_xor_sync(0xffffffffu, s, o);

    const float lse = m + __logf(s);

    if (lane == 0) {
        // element 0 of the row lives in lane 0's v0.x
        g_lpb[row] = v0.x - lse;
        if (u < UM1) {
            const int lab = labels[b * UM1 + u];
            const float xl = __ldg(acts + (size_t)row * VV + lab);  // L1/L2 hit
            g_lpl[bt * UM1 + u] = xl - lse;
        }
    }
}

// ---------------------------------------------------------------------------
// Kernel 2: alpha wavefront per batch. One CTA per b.
// Shared memory: lpb (T*U), lpl (T*UM1), two diagonal buffers.
// Anti-diagonal d = t+u: all cells on d depend only on d-1.
// Stops at the target diagonal t_idx + u_idx.
// ---------------------------------------------------------------------------
__global__ __launch_bounds__(128) void rnnt_alpha_kernel(
    const int* __restrict__ act_lens,
    const int* __restrict__ label_lens)
{
    extern __shared__ float sm[];
    float* lpb_s = sm;                       // T*U   = 16640 floats
    float* lpl_s = sm + TT * UU;             // T*UM1 = 16384 floats
    float* dbuf0 = lpl_s + TT * UM1;         // U floats
    float* dbuf1 = dbuf0 + UU;               // U floats

    const int b   = blockIdx.x;
    const int tid = threadIdx.x;

    // Stage per-batch lpb/lpl into shared (vectorized, coalesced).
    {
        const float4* src = reinterpret_cast<const float4*>(g_lpb + (size_t)b * TT * UU);
        float4* dst = reinterpret_cast<float4*>(lpb_s);
        for (int i = tid; i < (TT * UU) / 4; i += blockDim.x) dst[i] = src[i];
    }
    {
        const float4* src = reinterpret_cast<const float4*>(g_lpl + (size_t)b * TT * UM1);
        float4* dst = reinterpret_cast<float4*>(lpl_s);
        for (int i = tid; i < (TT * UM1) / 4; i += blockDim.x) dst[i] = src[i];
    }
    __syncthreads();

    const int t_tar = act_lens[b] - 1;
    const int u_tar = label_lens[b];
    const int d_tar = t_tar + u_tar;

    float* dA = dbuf0;   // diagonal d-1
    float* dB = dbuf1;   // diagonal d

    if (tid == 0) dA[0] = 0.f;   // alpha[0][0] = 0
    __syncthreads();

    for (int d = 1; d <= d_tar; ++d) {
        const int u = tid;
        // valid cells: 0 <= u <= min(d, U-1), t = d-u in [0, T-1]
        if (u < UU && u <= d && (d - u) <= (TT - 1)) {
            const int t = d - u;
            float top  = (t >= 1) ? dA[u]     + lpb_s[(t - 1) * UU + u]   : NEG_HUGE;
            float left = (u >= 1) ? dA[u - 1] + lpl_s[t * UM1 + (u - 1)]  : NEG_HUGE;
            const float mx = fmaxf(top, left);
            const float mn = fminf(top, left);
            const float val = mx + __logf(1.f + __expf(mn - mx));
            dB[u] = val;
            if (d == d_tar && u == u_tar) {
                // ll = alpha[t_tar][u_tar] + lp_blank[t_tar][u_tar]
                g_cost[b] = -(val + lpb_s[t * UU + u]);
            }
        }
        __syncthreads();
        float* tmp = dA; dA = dB; dB = tmp;
    }
}

// ---------------------------------------------------------------------------
// Kernel 3: deterministic finalize: out[0] = sum(costs)/B
// ---------------------------------------------------------------------------
__global__ void rnnt_finalize_kernel(float* __restrict__ out)
{
    float s = 0.f;
    #pragma unroll
    for (int b = 0; b < BB; ++b) s += g_cost[b];
    out[0] = s / (float)BB;
}

extern "C" void kernel_launch(void* const* d_in, const int* in_sizes, int n_in,
                              void* d_out, int out_size)
{
    const float* acts       = (const float*)d_in[0];
    const int*   labels     = (const int*)d_in[1];
    const int*   act_lens   = (const int*)d_in[2];
    const int*   label_lens = (const int*)d_in[3];
    float*       out        = (float*)d_out;

    // Kernel 1: one warp per (b,t,u) row
    {
        const int rows = BB * TT * UU;             // 133120
        const int warpsPerBlock = 8;               // 256 threads
        const int grid = (rows + warpsPerBlock - 1) / warpsPerBlock;
        rnnt_lse_kernel<<<grid, 256>>>(acts, labels);
    }

    // Kernel 2: wavefront, one CTA per batch, large dynamic smem
    {
        const size_t smem = (size_t)(TT * UU + TT * UM1 + 2 * UU) * sizeof(float);
        cudaFuncSetAttribute(rnnt_alpha_kernel,
                             cudaFuncAttributeMaxDynamicSharedMemorySize,
                             (int)smem);
        rnnt_alpha_kernel<<<BB, 128, smem>>>(act_lens, label_lens);
    }

    // Kernel 3: finalize
    rnnt_finalize_kernel<<<1, 1>>>(out);
}

// round 3
// speedup vs baseline: 1.0469x; 1.0469x over previous
#include <cuda_runtime.h>
#include <math.h>
#include <stdint.h>

// Problem constants (fixed-shape problem)
#define BB 8
#define TT 256
#define UU 65
#define VV 1024
#define UM1 64
#define SROW 66          // padded smem row stride: lane addr stride -65 = conflict-free

#define NEG_HUGE -1e30f

// Scratch (no cudaMalloc allowed)
__device__ float g_lpb[BB * TT * UU];    // log p(blank)  [b,t,u]
__device__ float g_lpl[BB * TT * UM1];   // log p(label)  [b,t,u]
__device__ float g_cost[BB];
__device__ unsigned int g_done;

// ---------------------------------------------------------------------------
// Kernel 1: per-(b,t,u) row logsumexp over V=1024 + gather blank/label logits.
// One warp per row, 8 float4 loads per lane. 86.9% DRAM — near roofline.
// Also resets the finalize ticket counter.
// ---------------------------------------------------------------------------
__global__ __launch_bounds__(256) void rnnt_lse_kernel(
    const float* __restrict__ acts,
    const int* __restrict__ labels)
{
    if (blockIdx.x == 0 && threadIdx.x == 0) g_done = 0u;

    const int warp = (blockIdx.x * blockDim.x + threadIdx.x) >> 5;
    const int lane = threadIdx.x & 31;
    if (warp >= BB * TT * UU) return;

    const int row = warp;                 // row = b*T*U + t*U + u
    const int u   = row % UU;
    const int bt  = row / UU;             // b*T + t
    const int b   = bt / TT;

    const float4* __restrict__ p =
        reinterpret_cast<const float4*>(acts) + (size_t)row * (VV / 4);

    float4 v0 = p[lane];
    float4 v1 = p[lane + 32];
    float4 v2 = p[lane + 64];
    float4 v3 = p[lane + 96];
    float4 v4 = p[lane + 128];
    float4 v5 = p[lane + 160];
    float4 v6 = p[lane + 192];
    float4 v7 = p[lane + 224];

    float m = v0.x;
    m = fmaxf(m, v0.y); m = fmaxf(m, v0.z); m = fmaxf(m, v0.w);
    m = fmaxf(m, v1.x); m = fmaxf(m, v1.y); m = fmaxf(m, v1.z); m = fmaxf(m, v1.w);
    m = fmaxf(m, v2.x); m = fmaxf(m, v2.y); m = fmaxf(m, v2.z); m = fmaxf(m, v2.w);
    m = fmaxf(m, v3.x); m = fmaxf(m, v3.y); m = fmaxf(m, v3.z); m = fmaxf(m, v3.w);
    m = fmaxf(m, v4.x); m = fmaxf(m, v4.y); m = fmaxf(m, v4.z); m = fmaxf(m, v4.w);
    m = fmaxf(m, v5.x); m = fmaxf(m, v5.y); m = fmaxf(m, v5.z); m = fmaxf(m, v5.w);
    m = fmaxf(m, v6.x); m = fmaxf(m, v6.y); m = fmaxf(m, v6.z); m = fmaxf(m, v6.w);
    m = fmaxf(m, v7.x); m = fmaxf(m, v7.y); m = fmaxf(m, v7.z); m = fmaxf(m, v7.w);

    #pragma unroll
    for (int o = 16; o > 0; o >>= 1)
        m = fmaxf(m, __shfl_xor_sync(0xffffffffu, m, o));

    float s = 0.f;
    s += __expf(v0.x - m); s += __expf(v0.y - m); s += __expf(v0.z - m); s += __expf(v0.w - m);
    s += __expf(v1.x - m); s += __expf(v1.y - m); s += __expf(v1.z - m); s += __expf(v1.w - m);
    s += __expf(v2.x - m); s += __expf(v2.y - m); s += __expf(v2.z - m); s += __expf(v2.w - m);
    s += __expf(v3.x - m); s += __expf(v3.y - m); s += __expf(v3.z - m); s += __expf(v3.w - m);
    s += __expf(v4.x - m); s += __expf(v4.y - m); s += __expf(v4.z - m); s += __expf(v4.w - m);
    s += __expf(v5.x - m); s += __expf(v5.y - m); s += __expf(v5.z - m); s += __expf(v5.w - m);
    s += __expf(v6.x - m); s += __expf(v6.y - m); s += __expf(v6.z - m); s += __expf(v6.w - m);
    s += __expf(v7.x - m); s += __expf(v7.y - m); s += __expf(v7.z - m); s += __expf(v7.w - m);

    #pragma unroll
    for (int o = 16; o > 0; o >>= 1)
        s += __shfl_xor_sync(0xffffffffu, s, o);

    const float lse = m + __logf(s);

    if (lane == 0) {
        g_lpb[row] = v0.x - lse;       // blank = element 0, lives in lane 0's v0.x
        if (u < UM1) {
            const int lab = labels[b * UM1 + u];
            const float xl = __ldg(acts + (size_t)row * VV + lab);
            g_lpl[bt * UM1 + u] = xl - lse;
        }
    }
}

// ---------------------------------------------------------------------------
// Kernel 2: register-resident anti-diagonal wavefront, ONE warp per batch.
// Lane L owns cells u=L (a0) and u=L+32 (a1); lane 31 also owns u=64 (a2).
// Cross-cell dependency A[u-1] via shfl_up — zero barriers in the main loop.
// lpb/lpl staged to smem by 4 warps (stride-66 rows -> conflict-free LDS).
// Finalize fused via threadfence + atomic ticket (counter reset in kernel 1).
// ---------------------------------------------------------------------------
__global__ __launch_bounds__(128) void rnnt_alpha_kernel(
    const int* __restrict__ act_lens,
    const int* __restrict__ label_lens,
    float* __restrict__ out)
{
    extern __shared__ float sm[];
    float* lpb_s = sm;                   // [TT][SROW], cols 0..64 used
    float* lpl_s = sm + TT * SROW;       // [TT][SROW], cols 0..63 used

    const int b   = blockIdx.x;
    const int tid = threadIdx.x;
    const int wrp = tid >> 5;
    const int ln  = tid & 31;

    // Stage per-batch lpb/lpl into padded smem (coalesced gmem, stride-1 STS).
    {
        const float* __restrict__ gb = g_lpb + (size_t)b * TT * UU;
        const float* __restrict__ gl = g_lpl + (size_t)b * TT * UM1;
        for (int r = wrp; r < TT; r += 4) {
            float* db = lpb_s + r * SROW;
            const float* sb = gb + r * UU;
            db[ln]      = sb[ln];
            db[ln + 32] = sb[ln + 32];
            if (ln == 0) db[64] = sb[64];
            float* dl = lpl_s + r * SROW;
            const float* sl = gl + r * UM1;
            dl[ln]      = sl[ln];
            dl[ln + 32] = sl[ln + 32];
        }
    }
    __syncthreads();
    if (wrp != 0) return;   // only warp 0 runs the wavefront

    const int t_tar = act_lens[b] - 1;
    const int u_tar = label_lens[b];
    const int d_tar = t_tar + u_tar;

    const unsigned FULL = 0xffffffffu;

    // Diagonal state in registers. Invalid cells held at NEG_HUGE.
    float a0 = (ln == 0) ? 0.f : NEG_HUGE;   // A[ln]
    float a1 = NEG_HUGE;                      // A[ln+32]
    float a2 = NEG_HUGE;                      // A[64] (lane 31 authoritative)

    const int lm1 = (ln == 0) ? 0 : (ln - 1);  // clamped u-1 index for lane's first cell

    #pragma unroll 2
    for (int d = 1; d <= d_tar; ++d) {
        float p0 = __shfl_up_sync(FULL, a0, 1);   // A[ln-1]
        float p1 = __shfl_up_sync(FULL, a1, 1);   // A[ln+31]
        float w  = __shfl_sync(FULL, a0, 31);     // A[31] (for lane 0's a1 cell)
        if (ln == 0) { p0 = NEG_HUGE; p1 = w; }

        // cell u0 = ln, t0 = d - ln
        const int t0  = d - ln;
        const int ib0 = min(max(t0 - 1, 0), TT - 1);
        const int il0 = min(max(t0,     0), TT - 1);
        const float top0 = a0 + lpb_s[ib0 * SROW + ln];
        const float lf0  = p0 + lpl_s[il0 * SROW + lm1];
        const float mx0 = fmaxf(top0, lf0);
        const float mn0 = fminf(top0, lf0);
        const float v0  = mx0 + __logf(1.f + __expf(mn0 - mx0));

        // cell u1 = ln + 32, t1 = t0 - 32
        const int t1  = t0 - 32;
        const int ib1 = min(max(t1 - 1, 0), TT - 1);
        const int il1 = min(max(t1,     0), TT - 1);
        const float top1 = a1 + lpb_s[ib1 * SROW + ln + 32];
        const float lf1  = p1 + lpl_s[il1 * SROW + ln + 31];
        const float mx1 = fmaxf(top1, lf1);
        const float mn1 = fminf(top1, lf1);
        const float v1  = mx1 + __logf(1.f + __expf(mn1 - mx1));

        // cell u2 = 64 (authoritative on lane 31; A[63] = old a1 of lane 31)
        const int t2  = d - 64;
        const int ib2 = min(max(t2 - 1, 0), TT - 1);
        const int il2 = min(max(t2,     0), TT - 1);
        const float top2 = a2 + lpb_s[ib2 * SROW + 64];
        const float lf2  = a1 + lpl_s[il2 * SROW + 63];
        const float mx2 = fmaxf(top2, lf2);
        const float mn2 = fminf(top2, lf2);
        const float v2  = mx2 + __logf(1.f + __expf(mn2 - mx2));

        a0 = (t0 >= 0) ? v0 : NEG_HUGE;
        a1 = (t1 >= 0) ? v1 : NEG_HUGE;
        a2 = (t2 >= 0) ? v2 : NEG_HUGE;
    }

    // Extract alpha[t_tar][u_tar] from the owning lane.
    float res = (u_tar == 64) ? a2 : ((u_tar >= 32) ? a1 : a0);
    const int src = (u_tar == 64) ? 31 : (u_tar & 31);
    res = __shfl_sync(FULL, res, src);

    if (ln == 0) {
        g_cost[b] = -(res + lpb_s[t_tar * SROW + u_tar]);
        __threadfence();
        const unsigned ticket = atomicAdd(&g_done, 1u);
        if (ticket == BB - 1) {
            __threadfence();
            float s = 0.f;
            #pragma unroll
            for (int i = 0; i < BB; ++i)
                s += *((volatile float*)&g_cost[i]);
            out[0] = s * (1.f / (float)BB);
        }
    }
}

extern "C" void kernel_launch(void* const* d_in, const int* in_sizes, int n_in,
                              void* d_out, int out_size)
{
    const float* acts       = (const float*)d_in[0];
    const int*   labels     = (const int*)d_in[1];
    const int*   act_lens   = (const int*)d_in[2];
    const int*   label_lens = (const int*)d_in[3];
    float*       out        = (float*)d_out;

    // Kernel 1: one warp per (b,t,u) row
    {
        const int rows = BB * TT * UU;             // 133120
        const int warpsPerBlock = 8;               // 256 threads
        const int grid = (rows + warpsPerBlock - 1) / warpsPerBlock;
        rnnt_lse_kernel<<<grid, 256>>>(acts, labels);
    }

    // Kernel 2: one warp-wavefront CTA per batch (+fused finalize)
    {
        const size_t smem = (size_t)(2 * TT * SROW) * sizeof(float);  // 135168 B
        cudaFuncSetAttribute(rnnt_alpha_kernel,
                             cudaFuncAttributeMaxDynamicSharedMemorySize,
                             (int)smem);
        rnnt_alpha_kernel<<<BB, 128, smem>>>(act_lens, label_lens, out);
    }
}

// round 9
// speedup vs baseline: 1.2175x; 1.1629x over previous
#include <cuda_runtime.h>
#include <math.h>
#include <stdint.h>

// Problem constants (fixed-shape problem)
#define BB 8
#define TT 256
#define UU 65
#define VV 1024
#define UM1 64
#define SROW 66            // padded smem row stride (words): lane stride -65 = -1 mod 32, conflict-free
#define GUARD 64           // guard rows below and above the valid t range
#define ROWS_TOT (TT + 2 * GUARD)   // 384 rows per table
#define EBIAS 64           // controller holds the DIAGONAL MAX at 2^EBIAS

// Scratch (no cudaMalloc allowed)
__device__ float g_pb[BB * TT * UU];    // p(blank)  [b,t,u]   (probability, not log)
__device__ float g_pl[BB * TT * UM1];   // p(label)  [b,t,u]   (probability, not log)
__device__ float g_cost[BB];
__device__ unsigned int g_done;

// ---------------------------------------------------------------------------
// Kernel 1: per-(b,t,u) row softmax stats over V=1024.
// Stores PROBABILITIES pb = exp(x_blank - lse), pl = exp(x_label - lse).
// One warp per row, 8 float4 loads per lane. 86.9% DRAM — near roofline.
// ---------------------------------------------------------------------------
__global__ __launch_bounds__(256) void rnnt_lse_kernel(
    const float* __restrict__ acts,
    const int* __restrict__ labels)
{
    if (blockIdx.x == 0 && threadIdx.x == 0) g_done = 0u;

    const int warp = (blockIdx.x * blockDim.x + threadIdx.x) >> 5;
    const int lane = threadIdx.x & 31;
    if (warp >= BB * TT * UU) return;

    const int row = warp;                 // row = b*T*U + t*U + u
    const int u   = row % UU;
    const int bt  = row / UU;             // b*T + t
    const int b   = bt / TT;

    const float4* __restrict__ p =
        reinterpret_cast<const float4*>(acts) + (size_t)row * (VV / 4);

    float4 v0 = p[lane];
    float4 v1 = p[lane + 32];
    float4 v2 = p[lane + 64];
    float4 v3 = p[lane + 96];
    float4 v4 = p[lane + 128];
    float4 v5 = p[lane + 160];
    float4 v6 = p[lane + 192];
    float4 v7 = p[lane + 224];

    float m = v0.x;
    m = fmaxf(m, v0.y); m = fmaxf(m, v0.z); m = fmaxf(m, v0.w);
    m = fmaxf(m, v1.x); m = fmaxf(m, v1.y); m = fmaxf(m, v1.z); m = fmaxf(m, v1.w);
    m = fmaxf(m, v2.x); m = fmaxf(m, v2.y); m = fmaxf(m, v2.z); m = fmaxf(m, v2.w);
    m = fmaxf(m, v3.x); m = fmaxf(m, v3.y); m = fmaxf(m, v3.z); m = fmaxf(m, v3.w);
    m = fmaxf(m, v4.x); m = fmaxf(m, v4.y); m = fmaxf(m, v4.z); m = fmaxf(m, v4.w);
    m = fmaxf(m, v5.x); m = fmaxf(m, v5.y); m = fmaxf(m, v5.z); m = fmaxf(m, v5.w);
    m = fmaxf(m, v6.x); m = fmaxf(m, v6.y); m = fmaxf(m, v6.z); m = fmaxf(m, v6.w);
    m = fmaxf(m, v7.x); m = fmaxf(m, v7.y); m = fmaxf(m, v7.z); m = fmaxf(m, v7.w);

    #pragma unroll
    for (int o = 16; o > 0; o >>= 1)
        m = fmaxf(m, __shfl_xor_sync(0xffffffffu, m, o));

    float s = 0.f;
    s += __expf(v0.x - m); s += __expf(v0.y - m); s += __expf(v0.z - m); s += __expf(v0.w - m);
    s += __expf(v1.x - m); s += __expf(v1.y - m); s += __expf(v1.z - m); s += __expf(v1.w - m);
    s += __expf(v2.x - m); s += __expf(v2.y - m); s += __expf(v2.z - m); s += __expf(v2.w - m);
    s += __expf(v3.x - m); s += __expf(v3.y - m); s += __expf(v3.z - m); s += __expf(v3.w - m);
    s += __expf(v4.x - m); s += __expf(v4.y - m); s += __expf(v4.z - m); s += __expf(v4.w - m);
    s += __expf(v5.x - m); s += __expf(v5.y - m); s += __expf(v5.z - m); s += __expf(v5.w - m);
    s += __expf(v6.x - m); s += __expf(v6.y - m); s += __expf(v6.z - m); s += __expf(v6.w - m);
    s += __expf(v7.x - m); s += __expf(v7.y - m); s += __expf(v7.z - m); s += __expf(v7.w - m);

    #pragma unroll
    for (int o = 16; o > 0; o >>= 1)
        s += __shfl_xor_sync(0xffffffffu, s, o);

    if (lane == 0) {
        const float inv_s = 1.0f / s;
        g_pb[row] = __expf(v0.x - m) * inv_s;   // blank prob (element 0 = lane0 v0.x)
        if (u < UM1) {
            const int lab = labels[b * UM1 + u];
            const float xl = __ldg(acts + (size_t)row * VV + lab);
            g_pl[bt * UM1 + u] = __expf(xl - m) * inv_s;
        }
    }
}

// ---------------------------------------------------------------------------
// Kernel 2: PROBABILITY-DOMAIN anti-diagonal wavefront, one warp per batch.
// Cell update: P_new[u] = P[u]*pb[t-1,u] + P[u-1]*pl[t,u-1]  (FMUL+FFMA only).
// Lane L owns u=L (P0) and u=L+32 (P1); lane 31 also owns u=64 (P2).
// LAG-1 DEADBEAT rescale regulating the TRUE DIAGONAL MAX (via
// REDUX.MAX.U32 on non-negative floats — bit order == value order),
// set-point 2^64: overflow would need +64 bits in one diagonal step
// (impossible); underflow only for cells >=190 bits below the max
// (negligible contributors). This replaces the R6 fixed-cell ref, which
// sat ~2^60-80 below interior cells (path-count tilt) and let them
// overflow to inf.
// Guard rows (all zeroed) eliminate index clamps: addresses are pure += SROW.
// Invalid cells stay exactly 0 and never feed valid cells.
// ---------------------------------------------------------------------------
__global__ __launch_bounds__(128) void rnnt_alpha_kernel(
    const int* __restrict__ act_lens,
    const int* __restrict__ label_lens,
    float* __restrict__ out)
{
    extern __shared__ float sm[];
    float* pb_tab = sm;                         // [ROWS_TOT][SROW]
    float* pl_tab = sm + ROWS_TOT * SROW;       // [ROWS_TOT][SROW]
    float* pb0 = pb_tab + GUARD * SROW;         // row t=0
    float* pl0 = pl_tab + GUARD * SROW;

    const int b   = blockIdx.x;
    const int tid = threadIdx.x;
    const int wrp = tid >> 5;
    const int ln  = tid & 31;

    // Zero ALL guard regions (below and above, both tables): any NaN pattern
    // in a guard word would poison invalid cells via 0*NaN.
    for (int i = tid; i < GUARD * SROW; i += 128) {
        pb_tab[i] = 0.f;
        pb_tab[(GUARD + TT) * SROW + i] = 0.f;
        pl_tab[i] = 0.f;
        pl_tab[(GUARD + TT) * SROW + i] = 0.f;
    }

    // Stage per-batch prob tables into padded smem (coalesced gmem reads).
    {
        const float* __restrict__ gb = g_pb + (size_t)b * TT * UU;
        const float* __restrict__ gl = g_pl + (size_t)b * TT * UM1;
        for (int r = wrp; r < TT; r += 4) {
            float* db = pb0 + r * SROW;
            const float* sb = gb + r * UU;
            db[ln]      = sb[ln];
            db[ln + 32] = sb[ln + 32];
            if (ln == 0) db[64] = sb[64];
            float* dl = pl0 + r * SROW;
            const float* sl = gl + r * UM1;
            dl[ln]      = sl[ln];
            dl[ln + 32] = sl[ln + 32];
        }
    }
    __syncthreads();
    if (wrp != 0) return;   // only warp 0 runs the wavefront

    const int t_tar = act_lens[b] - 1;
    const int u_tar = label_lens[b];
    const int d_tar = t_tar + u_tar;

    const unsigned FULL = 0xffffffffu;
    const int lm1 = (ln == 0) ? 0 : (ln - 1);

    // Diagonal state (probabilities). Invalid cells = 0.
    float P0 = (ln == 0) ? 1.f : 0.f;    // u = ln
    float P1 = 0.f;                       // u = ln+32
    float P2 = 0.f;                       // u = 64 (lane 31 authoritative)

    int   eacc = 0;          // sum of removed exponents
    float prevmax = 1.f;     // diagonal max of d-1 (lane-uniform via REDUX)

    // Per-lane smem pointers at d=1 (increment by SROW per diagonal).
    const float* q_ib0 = pb0 + (0   - ln) * SROW + ln;        // pb[t0-1][ln]
    const float* q_il0 = pl0 + (1   - ln) * SROW + lm1;       // pl[t0][ln-1]
    const float* q_ib1 = pb0 + (-32 - ln) * SROW + ln + 32;   // pb[t1-1][ln+32]
    const float* q_il1 = pl0 + (-31 - ln) * SROW + ln + 31;   // pl[t1][ln+31]
    const float* q_ib2 = pb0 + (-64) * SROW + 64;             // pb[t2-1][64]
    const float* q_il2 = pl0 + (-63) * SROW + 63;             // pl[t2][63]

    #pragma unroll 2
    for (int d = 1; d <= d_tar; ++d) {
        // pe = exponent(prevmax) - EBIAS; s = 2^-pe (exact power of 2).
        const int e  = ((__float_as_int(prevmax) >> 23) & 0xff) - 127;
        const int pe = min(max(e - EBIAS, -126), 126);
        const float s = __int_as_float((127 - pe) << 23);

        float p0 = __shfl_up_sync(FULL, P0, 1);   // P[ln-1]
        float p1 = __shfl_up_sync(FULL, P1, 1);   // P[ln+31]
        const float w = __shfl_sync(FULL, P0, 31);
        if (ln == 0) { p0 = 0.f; p1 = w; }

        const float n0 = fmaf(P0, *q_ib0, p0 * (*q_il0)) * s;
        const float n1 = fmaf(P1, *q_ib1, p1 * (*q_il1)) * s;
        const float n2 = fmaf(P2, *q_ib2, P1 * (*q_il2)) * s;   // left of u=64 is old P1(lane31)

        P0 = n0; P1 = n1; P2 = n2;
        eacc += pe;

        q_ib0 += SROW; q_il0 += SROW; q_ib1 += SROW;
        q_il1 += SROW; q_ib2 += SROW; q_il2 += SROW;

        // True diagonal max (all P >= 0 -> uint bit order == value order).
        // Lanes 0..30's P2 is a bounded mix of valid magnitudes (never
        // exceeds the real max materially); including it is safe.
        const float lmax = fmaxf(fmaxf(n0, n1), n2);
        prevmax = __uint_as_float(
            __reduce_max_sync(FULL, __float_as_uint(lmax)));
    }

    // Extract scaled P at (t_tar, u_tar).
    const float candt = (u_tar < 32) ? P0 : ((u_tar < 64) ? P1 : P2);
    const int   srct  = (u_tar < 64) ? (u_tar & 31) : 31;
    const float res   = __shfl_sync(FULL, candt, srct);

    if (ln == 0) {
        // alpha = log(res) + eacc*ln2 ; ll = alpha + log(pb[t_tar][u_tar])
        const float alpha = __logf(res) + (float)eacc * 0.69314718056f;
        g_cost[b] = -(alpha + __logf(pb0[t_tar * SROW + u_tar]));
        __threadfence();
        const unsigned ticket = atomicAdd(&g_done, 1u);
        if (ticket == BB - 1) {
            __threadfence();
            float acc = 0.f;
            #pragma unroll
            for (int i = 0; i < BB; ++i)
                acc += *((volatile float*)&g_cost[i]);
            out[0] = acc * (1.f / (float)BB);
        }
    }
}

extern "C" void kernel_launch(void* const* d_in, const int* in_sizes, int n_in,
                              void* d_out, int out_size)
{
    const float* acts       = (const float*)d_in[0];
    const int*   labels     = (const int*)d_in[1];
    const int*   act_lens   = (const int*)d_in[2];
    const int*   label_lens = (const int*)d_in[3];
    float*       out        = (float*)d_out;

    // Kernel 1: one warp per (b,t,u) row
    {
        const int rows = BB * TT * UU;             // 133120
        const int warpsPerBlock = 8;               // 256 threads
        const int grid = (rows + warpsPerBlock - 1) / warpsPerBlock;
        rnnt_lse_kernel<<<grid, 256>>>(acts, labels);
    }

    // Kernel 2: one warp-wavefront CTA per batch (+fused finalize)
    {
        const size_t smem = (size_t)(2 * ROWS_TOT * SROW) * sizeof(float);  // 202752 B
        cudaFuncSetAttribute(rnnt_alpha_kernel,
                             cudaFuncAttributeMaxDynamicSharedMemorySize,
                             (int)smem);
        rnnt_alpha_kernel<<<BB, 128, smem>>>(act_lens, label_lens, out);
    }
}

// round 10
// speedup vs baseline: 1.2182x; 1.0006x over previous
#include <cuda_runtime.h>
#include <math.h>
#include <stdint.h>

// Problem constants (fixed-shape problem)
#define BB 8
#define TT 256
#define UU 65
#define VV 1024
#define UM1 64
#define SROW 66            // padded smem row stride (words): lane stride -65 = -1 mod 32, conflict-free
#define GUARD 64           // guard rows below and above the valid t range
#define ROWS_TOT (TT + 2 * GUARD)   // 384 rows per table
#define EBIAS 64           // controller set-point: diagonal max held near 2^EBIAS

// Scratch (no cudaMalloc allowed)
__device__ float g_pb[BB * TT * UU];    // p(blank)  [b,t,u]   (probability, not log)
__device__ float g_pl[BB * TT * UM1];   // p(label)  [b,t,u]   (probability, not log)
__device__ float g_cost[BB];
__device__ unsigned int g_done;

// ---------------------------------------------------------------------------
// Kernel 1: per-(b,t,u) row softmax stats over V=1024.
// Stores PROBABILITIES pb = exp(x_blank - lse), pl = exp(x_label - lse).
// One warp per row, 8 float4 loads per lane. 86.9% DRAM — near roofline.
// ---------------------------------------------------------------------------
__global__ __launch_bounds__(256) void rnnt_lse_kernel(
    const float* __restrict__ acts,
    const int* __restrict__ labels)
{
    if (blockIdx.x == 0 && threadIdx.x == 0) g_done = 0u;

    const int warp = (blockIdx.x * blockDim.x + threadIdx.x) >> 5;
    const int lane = threadIdx.x & 31;
    if (warp >= BB * TT * UU) return;

    const int row = warp;                 // row = b*T*U + t*U + u
    const int u   = row % UU;
    const int bt  = row / UU;             // b*T + t
    const int b   = bt / TT;

    const float4* __restrict__ p =
        reinterpret_cast<const float4*>(acts) + (size_t)row * (VV / 4);

    float4 v0 = p[lane];
    float4 v1 = p[lane + 32];
    float4 v2 = p[lane + 64];
    float4 v3 = p[lane + 96];
    float4 v4 = p[lane + 128];
    float4 v5 = p[lane + 160];
    float4 v6 = p[lane + 192];
    float4 v7 = p[lane + 224];

    float m = v0.x;
    m = fmaxf(m, v0.y); m = fmaxf(m, v0.z); m = fmaxf(m, v0.w);
    m = fmaxf(m, v1.x); m = fmaxf(m, v1.y); m = fmaxf(m, v1.z); m = fmaxf(m, v1.w);
    m = fmaxf(m, v2.x); m = fmaxf(m, v2.y); m = fmaxf(m, v2.z); m = fmaxf(m, v2.w);
    m = fmaxf(m, v3.x); m = fmaxf(m, v3.y); m = fmaxf(m, v3.z); m = fmaxf(m, v3.w);
    m = fmaxf(m, v4.x); m = fmaxf(m, v4.y); m = fmaxf(m, v4.z); m = fmaxf(m, v4.w);
    m = fmaxf(m, v5.x); m = fmaxf(m, v5.y); m = fmaxf(m, v5.z); m = fmaxf(m, v5.w);
    m = fmaxf(m, v6.x); m = fmaxf(m, v6.y); m = fmaxf(m, v6.z); m = fmaxf(m, v6.w);
    m = fmaxf(m, v7.x); m = fmaxf(m, v7.y); m = fmaxf(m, v7.z); m = fmaxf(m, v7.w);

    #pragma unroll
    for (int o = 16; o > 0; o >>= 1)
        m = fmaxf(m, __shfl_xor_sync(0xffffffffu, m, o));

    float s = 0.f;
    s += __expf(v0.x - m); s += __expf(v0.y - m); s += __expf(v0.z - m); s += __expf(v0.w - m);
    s += __expf(v1.x - m); s += __expf(v1.y - m); s += __expf(v1.z - m); s += __expf(v1.w - m);
    s += __expf(v2.x - m); s += __expf(v2.y - m); s += __expf(v2.z - m); s += __expf(v2.w - m);
    s += __expf(v3.x - m); s += __expf(v3.y - m); s += __expf(v3.z - m); s += __expf(v3.w - m);
    s += __expf(v4.x - m); s += __expf(v4.y - m); s += __expf(v4.z - m); s += __expf(v4.w - m);
    s += __expf(v5.x - m); s += __expf(v5.y - m); s += __expf(v5.z - m); s += __expf(v5.w - m);
    s += __expf(v6.x - m); s += __expf(v6.y - m); s += __expf(v6.z - m); s += __expf(v6.w - m);
    s += __expf(v7.x - m); s += __expf(v7.y - m); s += __expf(v7.z - m); s += __expf(v7.w - m);

    #pragma unroll
    for (int o = 16; o > 0; o >>= 1)
        s += __shfl_xor_sync(0xffffffffu, s, o);

    if (lane == 0) {
        const float inv_s = 1.0f / s;
        g_pb[row] = __expf(v0.x - m) * inv_s;   // blank prob (element 0 = lane0 v0.x)
        if (u < UM1) {
            const int lab = labels[b * UM1 + u];
            const float xl = __ldg(acts + (size_t)row * VV + lab);
            g_pl[bt * UM1 + u] = __expf(xl - m) * inv_s;
        }
    }
}

// ---------------------------------------------------------------------------
// Kernel 2: PROBABILITY-DOMAIN anti-diagonal wavefront, one warp per batch.
// Cell update: P_new[u] = P[u]*pb[t-1,u] + P[u-1]*pl[t,u-1]  (FMUL+FFMA only).
// Lane L owns u=L (P0) and u=L+32 (P1); lane 31 also owns u=64 (P2).
//
// DAMPED LAG-2 controller on the TRUE DIAGONAL MAX:
//   pe_d = (exp2(max_{d-2}) - EBIAS) / 4   (gain 1/4)
// Closed loop x_d = x_{d-1} - (1/4) x_{d-2} + noise has a double root at
// 1/2: critically damped (the R5 lag-2 deadbeat had |lambda|=1 and blew
// up; the R9 lag-1 deadbeat was stable but put REDUX on the critical
// path -> ~200 cyc/diag). With 2 iterations of slack, REDUX(~30-40)+ALU
// fully overlaps the shfl+FFMA data chain (~38 cyc). Steady-state offset
// -4*dec ~ -30 bits, well inside the +-60-bit budget around 2^64.
//
// Guard rows (all zeroed) eliminate index clamps: addresses are pure += SROW.
// Invalid cells stay exactly 0 and never feed valid cells.
// ---------------------------------------------------------------------------
__global__ __launch_bounds__(128) void rnnt_alpha_kernel(
    const int* __restrict__ act_lens,
    const int* __restrict__ label_lens,
    float* __restrict__ out)
{
    extern __shared__ float sm[];
    float* pb_tab = sm;                         // [ROWS_TOT][SROW]
    float* pl_tab = sm + ROWS_TOT * SROW;       // [ROWS_TOT][SROW]
    float* pb0 = pb_tab + GUARD * SROW;         // row t=0
    float* pl0 = pl_tab + GUARD * SROW;

    const int b   = blockIdx.x;
    const int tid = threadIdx.x;
    const int wrp = tid >> 5;
    const int ln  = tid & 31;

    // Zero ALL guard regions (below and above, both tables): any NaN pattern
    // in a guard word would poison invalid cells via 0*NaN.
    for (int i = tid; i < GUARD * SROW; i += 128) {
        pb_tab[i] = 0.f;
        pb_tab[(GUARD + TT) * SROW + i] = 0.f;
        pl_tab[i] = 0.f;
        pl_tab[(GUARD + TT) * SROW + i] = 0.f;
    }

    // Stage per-batch prob tables into padded smem (coalesced gmem reads).
    {
        const float* __restrict__ gb = g_pb + (size_t)b * TT * UU;
        const float* __restrict__ gl = g_pl + (size_t)b * TT * UM1;
        for (int r = wrp; r < TT; r += 4) {
            float* db = pb0 + r * SROW;
            const float* sb = gb + r * UU;
            db[ln]      = sb[ln];
            db[ln + 32] = sb[ln + 32];
            if (ln == 0) db[64] = sb[64];
            float* dl = pl0 + r * SROW;
            const float* sl = gl + r * UM1;
            dl[ln]      = sl[ln];
            dl[ln + 32] = sl[ln + 32];
        }
    }
    __syncthreads();
    if (wrp != 0) return;   // only warp 0 runs the wavefront

    const int t_tar = act_lens[b] - 1;
    const int u_tar = label_lens[b];
    const int d_tar = t_tar + u_tar;

    const unsigned FULL = 0xffffffffu;
    const int lm1 = (ln == 0) ? 0 : (ln - 1);

    // Diagonal state (probabilities). Invalid cells = 0.
    float P0 = (ln == 0) ? 1.f : 0.f;    // u = ln
    float P1 = 0.f;                       // u = ln+32
    float P2 = 0.f;                       // u = 64 (lane 31 authoritative)

    int eacc = 0;            // sum of removed exponents
    // Max history (lane-uniform): m2 = max of diagonal d-2, m1 = of d-1.
    // Init at the set-point so early pe = 0 while max climbs up from 1.
    float m1 = __int_as_float((EBIAS + 127) << 23);
    float m2 = m1;

    // Per-lane smem pointers at d=1 (increment by SROW per diagonal;
    // under unroll these fold into LDS immediate offsets).
    const float* q_ib0 = pb0 + (0   - ln) * SROW + ln;        // pb[t0-1][ln]
    const float* q_il0 = pl0 + (1   - ln) * SROW + lm1;       // pl[t0][ln-1]
    const float* q_ib1 = pb0 + (-32 - ln) * SROW + ln + 32;   // pb[t1-1][ln+32]
    const float* q_il1 = pl0 + (-31 - ln) * SROW + ln + 31;   // pl[t1][ln+31]
    const float* q_ib2 = pb0 + (-64) * SROW + 64;             // pb[t2-1][64]
    const float* q_il2 = pl0 + (-63) * SROW + 63;             // pl[t2][63]

    #pragma unroll 4
    for (int d = 1; d <= d_tar; ++d) {
        // Controller (lag-2, gain 1/4): uses m2 = diagonal max of d-2.
        // Off the critical path: REDUX of d-1/d-2 had ~2 iterations to land.
        const int e  = ((__float_as_int(m2) >> 23) & 0xff) - 127;
        const int pe = min(max((e - EBIAS) >> 2, -126), 126);
        const float s = __int_as_float((127 - pe) << 23);

        float p0 = __shfl_up_sync(FULL, P0, 1);   // P[ln-1]
        float p1 = __shfl_up_sync(FULL, P1, 1);   // P[ln+31]
        const float w = __shfl_sync(FULL, P0, 31);
        if (ln == 0) { p0 = 0.f; p1 = w; }

        const float n0 = fmaf(P0, *q_ib0, p0 * (*q_il0)) * s;
        const float n1 = fmaf(P1, *q_ib1, p1 * (*q_il1)) * s;
        const float n2 = fmaf(P2, *q_ib2, P1 * (*q_il2)) * s;   // left of u=64 is old P1(lane31)

        P0 = n0; P1 = n1; P2 = n2;
        eacc += pe;

        q_ib0 += SROW; q_il0 += SROW; q_ib1 += SROW;
        q_il1 += SROW; q_ib2 += SROW; q_il2 += SROW;

        // True diagonal max (all P >= 0 -> uint bit order == value order).
        const float lmax = fmaxf(fmaxf(n0, n1), n2);
        m2 = m1;
        m1 = __uint_as_float(__reduce_max_sync(FULL, __float_as_uint(lmax)));
    }

    // Extract scaled P at (t_tar, u_tar).
    const float candt = (u_tar < 32) ? P0 : ((u_tar < 64) ? P1 : P2);
    const int   srct  = (u_tar < 64) ? (u_tar & 31) : 31;
    const float res   = __shfl_sync(FULL, candt, srct);

    if (ln == 0) {
        // alpha = log(res) + eacc*ln2 ; ll = alpha + log(pb[t_tar][u_tar])
        const float alpha = __logf(res) + (float)eacc * 0.69314718056f;
        g_cost[b] = -(alpha + __logf(pb0[t_tar * SROW + u_tar]));
        __threadfence();
        const unsigned ticket = atomicAdd(&g_done, 1u);
        if (ticket == BB - 1) {
            __threadfence();
            float acc = 0.f;
            #pragma unroll
            for (int i = 0; i < BB; ++i)
                acc += *((volatile float*)&g_cost[i]);
            out[0] = acc * (1.f / (float)BB);
        }
    }
}

extern "C" void kernel_launch(void* const* d_in, const int* in_sizes, int n_in,
                              void* d_out, int out_size)
{
    const float* acts       = (const float*)d_in[0];
    const int*   labels     = (const int*)d_in[1];
    const int*   act_lens   = (const int*)d_in[2];
    const int*   label_lens = (const int*)d_in[3];
    float*       out        = (float*)d_out;

    // Kernel 1: one warp per (b,t,u) row
    {
        const int rows = BB * TT * UU;             // 133120
        const int warpsPerBlock = 8;               // 256 threads
        const int grid = (rows + warpsPerBlock - 1) / warpsPerBlock;
        rnnt_lse_kernel<<<grid, 256>>>(acts, labels);
    }

    // Kernel 2: one warp-wavefront CTA per batch (+fused finalize)
    {
        const size_t smem = (size_t)(2 * ROWS_TOT * SROW) * sizeof(float);  // 202752 B
        cudaFuncSetAttribute(rnnt_alpha_kernel,
                             cudaFuncAttributeMaxDynamicSharedMemorySize,
                             (int)smem);
        rnnt_alpha_kernel<<<BB, 128, smem>>>(act_lens, label_lens, out);
    }
}

// round 11
// speedup vs baseline: 1.2396x; 1.0176x over previous
#include <cuda_runtime.h>
#include <math.h>
#include <stdint.h>

// Problem constants (fixed-shape problem)
#define BB 8
#define TT 256
#define UU 65
#define VV 1024
#define UM1 64
#define NDIAG 320          // t+u in [0, 319]
#define SK 68              // skewed-table row stride in words (even -> float2 aligned)
#define EBIAS 64           // controller set-point: diagonal max held near 2^EBIAS

// Scratch (no cudaMalloc allowed)
__device__ float g_pb[BB * TT * UU];    // p(blank)  [b,t,u]   (probability)
__device__ float g_pl[BB * TT * UM1];   // p(label)  [b,t,u]   (probability)
__device__ float g_cost[BB];
__device__ unsigned int g_done;

// ---------------------------------------------------------------------------
// Kernel 1: per-(b,t,u) row softmax stats over V=1024.
// Stores PROBABILITIES pb = exp(x_blank - lse), pl = exp(x_label - lse).
// One warp per row, 8 float4 loads per lane. 86.9% DRAM — near roofline.
// ---------------------------------------------------------------------------
__global__ __launch_bounds__(256) void rnnt_lse_kernel(
    const float* __restrict__ acts,
    const int* __restrict__ labels)
{
    if (blockIdx.x == 0 && threadIdx.x == 0) g_done = 0u;

    const int warp = (blockIdx.x * blockDim.x + threadIdx.x) >> 5;
    const int lane = threadIdx.x & 31;
    if (warp >= BB * TT * UU) return;

    const int row = warp;                 // row = b*T*U + t*U + u
    const int u   = row % UU;
    const int bt  = row / UU;             // b*T + t
    const int b   = bt / TT;

    const float4* __restrict__ p =
        reinterpret_cast<const float4*>(acts) + (size_t)row * (VV / 4);

    float4 v0 = p[lane];
    float4 v1 = p[lane + 32];
    float4 v2 = p[lane + 64];
    float4 v3 = p[lane + 96];
    float4 v4 = p[lane + 128];
    float4 v5 = p[lane + 160];
    float4 v6 = p[lane + 192];
    float4 v7 = p[lane + 224];

    float m = v0.x;
    m = fmaxf(m, v0.y); m = fmaxf(m, v0.z); m = fmaxf(m, v0.w);
    m = fmaxf(m, v1.x); m = fmaxf(m, v1.y); m = fmaxf(m, v1.z); m = fmaxf(m, v1.w);
    m = fmaxf(m, v2.x); m = fmaxf(m, v2.y); m = fmaxf(m, v2.z); m = fmaxf(m, v2.w);
    m = fmaxf(m, v3.x); m = fmaxf(m, v3.y); m = fmaxf(m, v3.z); m = fmaxf(m, v3.w);
    m = fmaxf(m, v4.x); m = fmaxf(m, v4.y); m = fmaxf(m, v4.z); m = fmaxf(m, v4.w);
    m = fmaxf(m, v5.x); m = fmaxf(m, v5.y); m = fmaxf(m, v5.z); m = fmaxf(m, v5.w);
    m = fmaxf(m, v6.x); m = fmaxf(m, v6.y); m = fmaxf(m, v6.z); m = fmaxf(m, v6.w);
    m = fmaxf(m, v7.x); m = fmaxf(m, v7.y); m = fmaxf(m, v7.z); m = fmaxf(m, v7.w);

    #pragma unroll
    for (int o = 16; o > 0; o >>= 1)
        m = fmaxf(m, __shfl_xor_sync(0xffffffffu, m, o));

    float s = 0.f;
    s += __expf(v0.x - m); s += __expf(v0.y - m); s += __expf(v0.z - m); s += __expf(v0.w - m);
    s += __expf(v1.x - m); s += __expf(v1.y - m); s += __expf(v1.z - m); s += __expf(v1.w - m);
    s += __expf(v2.x - m); s += __expf(v2.y - m); s += __expf(v2.z - m); s += __expf(v2.w - m);
    s += __expf(v3.x - m); s += __expf(v3.y - m); s += __expf(v3.z - m); s += __expf(v3.w - m);
    s += __expf(v4.x - m); s += __expf(v4.y - m); s += __expf(v4.z - m); s += __expf(v4.w - m);
    s += __expf(v5.x - m); s += __expf(v5.y - m); s += __expf(v5.z - m); s += __expf(v5.w - m);
    s += __expf(v6.x - m); s += __expf(v6.y - m); s += __expf(v6.z - m); s += __expf(v6.w - m);
    s += __expf(v7.x - m); s += __expf(v7.y - m); s += __expf(v7.z - m); s += __expf(v7.w - m);

    #pragma unroll
    for (int o = 16; o > 0; o >>= 1)
        s += __shfl_xor_sync(0xffffffffu, s, o);

    if (lane == 0) {
        const float inv_s = 1.0f / s;
        g_pb[row] = __expf(v0.x - m) * inv_s;   // blank prob (element 0 = lane0 v0.x)
        if (u < UM1) {
            const int lab = labels[b * UM1 + u];
            const float xl = __ldg(acts + (size_t)row * VV + lab);
            g_pl[bt * UM1 + u] = __expf(xl - m) * inv_s;
        }
    }
}

// ---------------------------------------------------------------------------
// Kernel 2: prob-domain wavefront with PAIRED lane mapping + SKEWED tables.
// Lane L owns u=2L (Pe) and u=2L+1 (Po); lane 31 also owns u=64 (P2).
//   n_e = Pe*pb + shfl(Po)*pl ; n_o = Po*pb' + Pe*pl' ; n_2 = P2*pb64 + Po*pl64
// Only ONE shfl per diagonal, and it alternates with an in-lane hop:
// carried cycle = (shfl+FFMA) + (FFMA) per 2 diagonals ~ 27 cyc/diag.
// Skewed tables pbS[t+u][u], plS[t+u][u]=pl[t][u-1]: all operands of
// diagonal d sit in rows d-1 / d -> two aligned float2 LDS per lane from a
// single row (conflict-free); out-of-range entries are ZERO by zero-fill,
// so boundary/guard handling is automatic and invalid cells stay exactly 0.
// Controller: damped lag-3 (gain 1/4; roots -0.43, 0.76e^{+-i t}: stable)
// on the REDUX diagonal max — ~3 iterations of slack vs REDUX latency.
// ---------------------------------------------------------------------------
__global__ __launch_bounds__(128) void rnnt_alpha_kernel(
    const int* __restrict__ act_lens,
    const int* __restrict__ label_lens,
    float* __restrict__ out)
{
    extern __shared__ float sm[];
    float* pbS = sm;                    // [NDIAG][SK]: pbS[j][u] = pb[j-u][u]
    float* plS = sm + NDIAG * SK;       // [NDIAG][SK]: plS[j][u] = pl[j-u][u-1]

    const int b   = blockIdx.x;
    const int tid = threadIdx.x;
    const int wrp = tid >> 5;
    const int ln  = tid & 31;

    // Zero-fill both tables (out-of-range == 0 is the boundary condition).
    {
        float4* z = reinterpret_cast<float4*>(sm);
        const int n4 = (2 * NDIAG * SK) / 4;
        for (int i = tid; i < n4; i += 128)
            z[i] = make_float4(0.f, 0.f, 0.f, 0.f);
    }
    __syncthreads();

    // Fill skewed tables (coalesced gmem reads; smem lane stride SK+1=69
    // ~ 5 mod 32 -> conflict-free scatter).
    {
        const float* __restrict__ gb = g_pb + (size_t)b * TT * UU;
        const float* __restrict__ gl = g_pl + (size_t)b * TT * UM1;
        for (int t = wrp; t < TT; t += 4) {
            const float* sb = gb + t * UU;
            // pbS[(t+u)*SK + u] = pb[t][u], u = ln, ln+32, 64
            pbS[(t + ln) * SK + ln]           = sb[ln];
            pbS[(t + ln + 32) * SK + ln + 32] = sb[ln + 32];
            if (ln == 0) pbS[(t + 64) * SK + 64] = sb[64];
            // plS[(t+u)*SK + u] = pl[t][u-1], u = ln+1, ln+33
            const float* sl = gl + t * UM1;
            plS[(t + ln + 1) * SK + ln + 1]   = sl[ln];
            plS[(t + ln + 33) * SK + ln + 33] = sl[ln + 32];
        }
    }
    __syncthreads();
    if (wrp != 0) return;   // only warp 0 runs the wavefront

    const int t_tar = act_lens[b] - 1;
    const int u_tar = label_lens[b];
    const int d_tar = t_tar + u_tar;

    const unsigned FULL = 0xffffffffu;

    // Diagonal state. Lane L: Pe = A[2L], Po = A[2L+1]; lane31 also P2 = A[64].
    float Pe = (ln == 0) ? 1.f : 0.f;
    float Po = 0.f;
    float P2 = 0.f;

    int eacc = 0;
    // Max history for lag-3 controller (init at set-point -> early pe = 0).
    float mh1 = __int_as_float((EBIAS + 127) << 23);
    float mh2 = mh1, mh3 = mh1;

    const float2* pb_row = reinterpret_cast<const float2*>(pbS) + ln;          // row d-1=0
    const float2* pl_row = reinterpret_cast<const float2*>(plS + SK) + ln;     // row d=1
    const float*  pb64p  = pbS + 64;            // + (d-1)*SK
    const float*  pl64p  = plS + SK + 64;       // + (d-1)*SK  (row d)

    #pragma unroll 4
    for (int d = 1; d <= d_tar; ++d) {
        // Controller (lag-3, gain 1/4) — far off the critical path.
        const int e  = ((__float_as_int(mh3) >> 23) & 0xff) - 127;
        const int pe = min(max((e - EBIAS) >> 2, -126), 126);
        const float s = __int_as_float((127 - pe) << 23);

        float po = __shfl_up_sync(FULL, Po, 1);   // A[2L-1]
        if (ln == 0) po = 0.f;

        const float2 pbv = *pb_row;    // pb terms for u=2L, 2L+1 (row d-1)
        const float2 plv = *pl_row;    // pl terms for u=2L, 2L+1 (row d)
        const float pb64 = *pb64p;
        const float pl64 = *pl64p;

        const float ne = fmaf(Pe, pbv.x, po * plv.x) * s;
        const float no = fmaf(Po, pbv.y, Pe * plv.y) * s;
        const float n2 = fmaf(P2, pb64,  Po * pl64) * s;   // meaningful on lane31

        Pe = ne; Po = no; P2 = n2;
        eacc += pe;

        pb_row += SK / 2; pl_row += SK / 2;
        pb64p  += SK;     pl64p  += SK;

        // Diagonal max via REDUX (non-negative floats: uint order == value order).
        const float lmax = fmaxf(fmaxf(ne, no), n2);
        mh3 = mh2; mh2 = mh1;
        mh1 = __uint_as_float(__reduce_max_sync(FULL, __float_as_uint(lmax)));
    }

    // Extract scaled P at (t_tar, u_tar).
    float cand;
    int src;
    if (u_tar == 64)      { cand = P2; src = 31; }
    else if (u_tar & 1)   { cand = Po; src = u_tar >> 1; }
    else                  { cand = Pe; src = u_tar >> 1; }
    const float res = __shfl_sync(FULL, cand, src);

    if (ln == 0) {
        // alpha = log(res) + eacc*ln2 ; ll = alpha + log(pb[t_tar][u_tar])
        const float alpha = __logf(res) + (float)eacc * 0.69314718056f;
        const float pbt = pbS[d_tar * SK + u_tar];   // pb[t_tar][u_tar]
        g_cost[b] = -(alpha + __logf(pbt));
        __threadfence();
        const unsigned ticket = atomicAdd(&g_done, 1u);
        if (ticket == BB - 1) {
            __threadfence();
            float acc = 0.f;
            #pragma unroll
            for (int i = 0; i < BB; ++i)
                acc += *((volatile float*)&g_cost[i]);
            out[0] = acc * (1.f / (float)BB);
        }
    }
}

extern "C" void kernel_launch(void* const* d_in, const int* in_sizes, int n_in,
                              void* d_out, int out_size)
{
    const float* acts       = (const float*)d_in[0];
    const int*   labels     = (const int*)d_in[1];
    const int*   act_lens   = (const int*)d_in[2];
    const int*   label_lens = (const int*)d_in[3];
    float*       out        = (float*)d_out;

    // Kernel 1: one warp per (b,t,u) row
    {
        const int rows = BB * TT * UU;             // 133120
        const int warpsPerBlock = 8;               // 256 threads
        const int grid = (rows + warpsPerBlock - 1) / warpsPerBlock;
        rnnt_lse_kernel<<<grid, 256>>>(acts, labels);
    }

    // Kernel 2: paired-lane wavefront on skewed tables (+fused finalize)
    {
        const size_t smem = (size_t)(2 * NDIAG * SK) * sizeof(float);  // 174080 B
        cudaFuncSetAttribute(rnnt_alpha_kernel,
                             cudaFuncAttributeMaxDynamicSharedMemorySize,
                             (int)smem);
        rnnt_alpha_kernel<<<BB, 128, smem>>>(act_lens, label_lens, out);
    }
}